// round 14
// baseline (speedup 1.0000x reference)
#include <cuda_runtime.h>
#include <cuda_fp16.h>
#include <cstdint>

// out = relu(x @ W_w^T + W_b)   (attention collapses: softmax rows sum to 1).
//
// R14: occupancy doubling. R10-R13 (four feeding architectures) all tie at
// ~29us with issue<=23% -> the shared constraint is 16 warps/SM, not the
// pipeline shape. Shrink CTA to BM=64 (acc 16 regs, stage 10.2 KB) and run
// 4 CTAs/SM = 32 warps/SM. Skeleton = R10 (fp16 single-product, double
// buffer, reg prefetch, 1 barrier/chunk). rel_err must stay 2.944e-4.

#define D_DIM 256
#define BM 64
#define BN 64
#define BK 32
#define N_CHUNKS (D_DIM / BK)      // 8
#define ROWB 80                    // (32+8) fp16 row stride: conflict-free ldsm

#define OFF_A 0
#define OFF_B (BM * ROWB)                 // 5120
#define STAGE_BYTES (OFF_B + BN * ROWB)   // 10240
#define SMEM_TOTAL (2 * STAGE_BYTES)      // 20480

__device__ __forceinline__ uint32_t smem_u32(const void* p) {
    uint32_t a;
    asm("{ .reg .u64 t; cvta.to.shared.u64 t, %1; cvt.u32.u64 %0, t; }" : "=r"(a) : "l"(p));
    return a;
}

__device__ __forceinline__ void ldsm_x4(uint32_t* r, uint32_t addr) {
    asm volatile("ldmatrix.sync.aligned.m8n8.x4.shared.b16 {%0,%1,%2,%3}, [%4];"
                 : "=r"(r[0]), "=r"(r[1]), "=r"(r[2]), "=r"(r[3]) : "r"(addr));
}

__device__ __forceinline__ void mma_f16(float* d, const uint32_t* a, const uint32_t* b) {
    asm volatile("mma.sync.aligned.m16n8k16.row.col.f32.f16.f16.f32 "
                 "{%0,%1,%2,%3}, {%4,%5,%6,%7}, {%8,%9}, {%0,%1,%2,%3};"
                 : "+f"(d[0]), "+f"(d[1]), "+f"(d[2]), "+f"(d[3])
                 : "r"(a[0]), "r"(a[1]), "r"(a[2]), "r"(a[3]),
                   "r"(b[0]), "r"(b[1]));
}

// float4 -> fp16x4, one 8 B store.
__device__ __forceinline__ void cvt_store(uint32_t addr, float4 v) {
    __half2 h0 = __floats2half2_rn(v.x, v.y);
    __half2 h1 = __floats2half2_rn(v.z, v.w);
    uint32_t h0u = *(uint32_t*)&h0, h1u = *(uint32_t*)&h1;
    asm volatile("st.shared.v2.b32 [%0], {%1, %2};" :: "r"(addr), "r"(h0u), "r"(h1u) : "memory");
}

__global__ __launch_bounds__(256, 4)
void fcgat_hmma(const float* __restrict__ A,     // x  [32768, 256]
                const float* __restrict__ W,     // W  [256, 256]
                const float* __restrict__ bias,  // [256]
                float* __restrict__ C)           // [32768, 256]
{
    extern __shared__ __align__(16) unsigned char smem[];
    const uint32_t sb = smem_u32(smem);

    const int t   = threadIdx.x;
    const int l   = t & 31;
    const int wid = t >> 5;
    const int wm  = wid & 3;          // 4 warps along M (16 rows each)
    const int wn  = wid >> 2;         // 2 warps along N (32 cols each)
    const int m0  = wm * 16;
    const int n0  = wn * 32;

    const float* Ag = A + (size_t)blockIdx.y * BM * D_DIM;
    const float* Bg = W + (size_t)blockIdx.x * BN * D_DIM;

    float acc[4][4];
    #pragma unroll
    for (int j = 0; j < 4; j++)
        #pragma unroll
        for (int c = 0; c < 4; c++)
            acc[j][c] = 0.0f;

    const uint32_t a_lane = (uint32_t)((m0 + (l & 15)) * ROWB + (l >> 4) * 16);
    const uint32_t b_lane = (uint32_t)((n0 + (l & 7) + ((l >> 4) << 3)) * ROWB
                                       + ((l >> 3) & 1) * 16);

    // Per-chunk loads: A 64 rows x 8 float4 = 512 -> 2/thread; B same.
    float4 pa[2], pb[2];

    // ---- prologue: load + store chunk 0 ----
    #pragma unroll
    for (int i = 0; i < 2; i++) {
        int idx = t + i * 256;
        pa[i] = *(const float4*)(Ag + (size_t)(idx >> 3) * D_DIM + (idx & 7) * 4);
        pb[i] = *(const float4*)(Bg + (size_t)(idx >> 3) * D_DIM + (idx & 7) * 4);
    }
    #pragma unroll
    for (int i = 0; i < 2; i++) {
        int idx = t + i * 256;
        uint32_t so = (uint32_t)((idx >> 3) * ROWB + (idx & 7) * 8);
        cvt_store(sb + OFF_A + so, pa[i]);
        cvt_store(sb + OFF_B + so, pb[i]);
    }
    __syncthreads();

    uint32_t stage = 0;
    for (int ch = 0; ch < N_CHUNKS; ch++) {
        const bool more = (ch + 1 < N_CHUNKS);
        const int kn = (ch + 1) * BK;

        // (1) issue next chunk's global loads
        if (more) {
            #pragma unroll
            for (int i = 0; i < 2; i++) {
                int idx = t + i * 256;
                pa[i] = *(const float4*)(Ag + (size_t)(idx >> 3) * D_DIM + kn + (idx & 7) * 4);
                pb[i] = *(const float4*)(Bg + (size_t)(idx >> 3) * D_DIM + kn + (idx & 7) * 4);
            }
        }

        // (2) compute current chunk
        const uint32_t base = sb + stage;
        #pragma unroll
        for (int ks = 0; ks < 2; ks++) {
            const uint32_t ko = (uint32_t)(ks * 32);   // 16 fp16 = 32 B
            uint32_t ah[4], bh[2][4];
            ldsm_x4(ah, base + OFF_A + a_lane + ko);
            #pragma unroll
            for (int jp = 0; jp < 2; jp++)
                ldsm_x4(bh[jp], base + OFF_B + b_lane + ko + jp * 16 * ROWB);

            #pragma unroll
            for (int j = 0; j < 4; j++)
                mma_f16(acc[j], ah, bh[j >> 1] + (j & 1) * 2);
        }

        // (3) convert + store next chunk into the other stage
        if (more) {
            const uint32_t nbase = sb + (stage ^ STAGE_BYTES);
            #pragma unroll
            for (int i = 0; i < 2; i++) {
                int idx = t + i * 256;
                uint32_t so = (uint32_t)((idx >> 3) * ROWB + (idx & 7) * 8);
                cvt_store(nbase + OFF_A + so, pa[i]);
                cvt_store(nbase + OFF_B + so, pb[i]);
            }
        }

        // (4) single barrier per chunk
        __syncthreads();
        stage ^= STAGE_BYTES;
    }

    // ---- epilogue: bias + relu ----
    const int g  = l >> 2;
    const int tc = l & 3;
    const size_t r0 = (size_t)blockIdx.y * BM + m0 + g;
    const size_t r1 = r0 + 8;
    #pragma unroll
    for (int j = 0; j < 4; j++) {
        const int col = blockIdx.x * BN + n0 + 8 * j + 2 * tc;
        float2 bv = *(const float2*)(bias + col);
        float2 o0, o1;
        o0.x = fmaxf(acc[j][0] + bv.x, 0.0f);
        o0.y = fmaxf(acc[j][1] + bv.y, 0.0f);
        o1.x = fmaxf(acc[j][2] + bv.x, 0.0f);
        o1.y = fmaxf(acc[j][3] + bv.y, 0.0f);
        *(float2*)(C + r0 * D_DIM + col) = o0;
        *(float2*)(C + r1 * D_DIM + col) = o1;
    }
}

extern "C" void kernel_launch(void* const* d_in, const int* in_sizes, int n_in,
                              void* d_out, int out_size)
{
    const float* x   = (const float*)d_in[0];
    const float* W_w = (const float*)d_in[1];
    const float* W_b = (const float*)d_in[2];
    float* out = (float*)d_out;

    int M = in_sizes[0] / D_DIM;                  // 32768
    cudaFuncSetAttribute(fcgat_hmma,
                         cudaFuncAttributeMaxDynamicSharedMemorySize, SMEM_TOTAL);
    dim3 grid(D_DIM / BN, M / BM);                // (4, 512) = 2048 CTAs
    fcgat_hmma<<<grid, 256, SMEM_TOTAL>>>(x, W_w, W_b, out);
}

// round 15
// speedup vs baseline: 1.3611x; 1.3611x over previous
#include <cuda_runtime.h>
#include <cuda_fp16.h>
#include <cstdint>

// out = relu(x @ W_w^T + W_b)   (attention collapses: softmax rows sum to 1).
//
// R15 = R10 skeleton (fp16 single-product, 8 warps 4x2, warp 32x32, double
// buffer, reg prefetch, 1 barrier/chunk) + PERSISTENT B:
//   B (64x256 weight slice) is loop-invariant -> converted to fp16 smem once
//   in the prologue; B LDG/STS deleted from the mainloop.
// L1-wavefront model (validated on R10/R11/R13/R14): loop L1 work -22%.
// rel_err must stay bit-identical 2.944e-4.

#define D_DIM 256
#define BM 128
#define BN 64
#define BK 32
#define N_CHUNKS (D_DIM / BK)      // 8
#define ROWB 80                    // A stage row stride: (32+8) fp16, conflict-free
#define ROWB_B 528                 // persistent B row stride: (256+8) fp16, conflict-free

#define A_STAGE (BM * ROWB)                 // 10240
#define OFF_B (2 * A_STAGE)                 // 20480
#define SMEM_TOTAL (OFF_B + BN * ROWB_B)    // 54272

__device__ __forceinline__ uint32_t smem_u32(const void* p) {
    uint32_t a;
    asm("{ .reg .u64 t; cvta.to.shared.u64 t, %1; cvt.u32.u64 %0, t; }" : "=r"(a) : "l"(p));
    return a;
}

__device__ __forceinline__ void ldsm_x4(uint32_t* r, uint32_t addr) {
    asm volatile("ldmatrix.sync.aligned.m8n8.x4.shared.b16 {%0,%1,%2,%3}, [%4];"
                 : "=r"(r[0]), "=r"(r[1]), "=r"(r[2]), "=r"(r[3]) : "r"(addr));
}

__device__ __forceinline__ void mma_f16(float* d, const uint32_t* a, const uint32_t* b) {
    asm volatile("mma.sync.aligned.m16n8k16.row.col.f32.f16.f16.f32 "
                 "{%0,%1,%2,%3}, {%4,%5,%6,%7}, {%8,%9}, {%0,%1,%2,%3};"
                 : "+f"(d[0]), "+f"(d[1]), "+f"(d[2]), "+f"(d[3])
                 : "r"(a[0]), "r"(a[1]), "r"(a[2]), "r"(a[3]),
                   "r"(b[0]), "r"(b[1]));
}

// float4 -> fp16x4, one 8 B store.
__device__ __forceinline__ void cvt_store(uint32_t addr, float4 v) {
    __half2 h0 = __floats2half2_rn(v.x, v.y);
    __half2 h1 = __floats2half2_rn(v.z, v.w);
    uint32_t h0u = *(uint32_t*)&h0, h1u = *(uint32_t*)&h1;
    asm volatile("st.shared.v2.b32 [%0], {%1, %2};" :: "r"(addr), "r"(h0u), "r"(h1u) : "memory");
}

__global__ __launch_bounds__(256, 2)
void fcgat_hmma(const float* __restrict__ A,     // x  [32768, 256]
                const float* __restrict__ W,     // W  [256, 256]
                const float* __restrict__ bias,  // [256]
                float* __restrict__ C)           // [32768, 256]
{
    extern __shared__ __align__(16) unsigned char smem[];
    const uint32_t sb = smem_u32(smem);

    const int t   = threadIdx.x;
    const int l   = t & 31;
    const int wid = t >> 5;
    const int wm  = wid & 3;          // 4 warps along M
    const int wn  = wid >> 2;         // 2 warps along N
    const int m0  = wm * 32;
    const int n0  = wn * 32;

    const float* Ag = A + (size_t)blockIdx.y * BM * D_DIM;
    const float* Bg = W + (size_t)blockIdx.x * BN * D_DIM;

    float acc[2][4][4];
    #pragma unroll
    for (int i = 0; i < 2; i++)
        #pragma unroll
        for (int j = 0; j < 4; j++)
            #pragma unroll
            for (int c = 0; c < 4; c++)
                acc[i][j][c] = 0.0f;

    const uint32_t a_lane = (uint32_t)((m0 + (l & 15)) * ROWB + (l >> 4) * 16);
    const uint32_t b_lane = (uint32_t)((n0 + (l & 7) + ((l >> 4) << 3)) * ROWB_B
                                       + ((l >> 3) & 1) * 16);

    float4 pa[4];

    // ---- prologue ----
    // A chunk-0 loads first (their latency overlaps the B preload below).
    #pragma unroll
    for (int i = 0; i < 4; i++) {
        int idx = t + i * 256;
        pa[i] = *(const float4*)(Ag + (size_t)(idx >> 3) * D_DIM + (idx & 7) * 4);
    }
    // Persistent B: 64 rows x 64 float4 = 4096 -> 16/thread, fp16 convert once.
    #pragma unroll
    for (int i = 0; i < 16; i++) {
        int idx = t + i * 256;
        int row = idx >> 6;            // 0..63
        int c4  = idx & 63;            // 0..63
        float4 v = *(const float4*)(Bg + (size_t)row * D_DIM + c4 * 4);
        cvt_store(sb + OFF_B + (uint32_t)(row * ROWB_B + c4 * 8), v);
    }
    // Stage A chunk 0.
    #pragma unroll
    for (int i = 0; i < 4; i++) {
        int idx = t + i * 256;
        uint32_t so = (uint32_t)((idx >> 3) * ROWB + (idx & 7) * 8);
        cvt_store(sb + so, pa[i]);
    }
    __syncthreads();

    uint32_t stage = 0;
    for (int ch = 0; ch < N_CHUNKS; ch++) {
        const bool more = (ch + 1 < N_CHUNKS);
        const int kn = (ch + 1) * BK;

        // (1) issue next A chunk's global loads (latency hidden behind MMAs)
        if (more) {
            #pragma unroll
            for (int i = 0; i < 4; i++) {
                int idx = t + i * 256;
                pa[i] = *(const float4*)(Ag + (size_t)(idx >> 3) * D_DIM + kn + (idx & 7) * 4);
            }
        }

        // (2) compute current chunk: A from stage ring, B from persistent smem
        const uint32_t abase = sb + stage;
        #pragma unroll
        for (int ks = 0; ks < 2; ks++) {
            const uint32_t koA = (uint32_t)(ks * 32);              // 16 fp16 = 32 B
            const uint32_t koB = (uint32_t)(ch * 64 + ks * 32);    // within full-K B row
            uint32_t ah[2][4], bh[2][4];
            #pragma unroll
            for (int i = 0; i < 2; i++)
                ldsm_x4(ah[i], abase + a_lane + koA + i * 16 * ROWB);
            #pragma unroll
            for (int jp = 0; jp < 2; jp++)
                ldsm_x4(bh[jp], sb + OFF_B + b_lane + koB + jp * 16 * ROWB_B);

            #pragma unroll
            for (int i = 0; i < 2; i++)
                #pragma unroll
                for (int j = 0; j < 4; j++)
                    mma_f16(acc[i][j], ah[i], bh[j >> 1] + (j & 1) * 2);
        }

        // (3) convert + store next A chunk into the other stage
        if (more) {
            const uint32_t nbase = sb + (stage ^ A_STAGE);
            #pragma unroll
            for (int i = 0; i < 4; i++) {
                int idx = t + i * 256;
                uint32_t so = (uint32_t)((idx >> 3) * ROWB + (idx & 7) * 8);
                cvt_store(nbase + so, pa[i]);
            }
        }

        // (4) single barrier per chunk
        __syncthreads();
        stage ^= A_STAGE;
    }

    // ---- epilogue: bias + relu ----
    const int g  = l >> 2;
    const int tc = l & 3;
    #pragma unroll
    for (int i = 0; i < 2; i++) {
        const size_t r0 = (size_t)blockIdx.y * BM + m0 + 16 * i + g;
        const size_t r1 = r0 + 8;
        #pragma unroll
        for (int j = 0; j < 4; j++) {
            const int col = blockIdx.x * BN + n0 + 8 * j + 2 * tc;
            float2 bv = *(const float2*)(bias + col);
            float2 o0, o1;
            o0.x = fmaxf(acc[i][j][0] + bv.x, 0.0f);
            o0.y = fmaxf(acc[i][j][1] + bv.y, 0.0f);
            o1.x = fmaxf(acc[i][j][2] + bv.x, 0.0f);
            o1.y = fmaxf(acc[i][j][3] + bv.y, 0.0f);
            *(float2*)(C + r0 * D_DIM + col) = o0;
            *(float2*)(C + r1 * D_DIM + col) = o1;
        }
    }
}

extern "C" void kernel_launch(void* const* d_in, const int* in_sizes, int n_in,
                              void* d_out, int out_size)
{
    const float* x   = (const float*)d_in[0];
    const float* W_w = (const float*)d_in[1];
    const float* W_b = (const float*)d_in[2];
    float* out = (float*)d_out;

    int M = in_sizes[0] / D_DIM;                  // 32768
    cudaFuncSetAttribute(fcgat_hmma,
                         cudaFuncAttributeMaxDynamicSharedMemorySize, SMEM_TOTAL);
    dim3 grid(D_DIM / BN, M / BM);                // (4, 256) = 1024 CTAs
    fcgat_hmma<<<grid, 256, SMEM_TOTAL>>>(x, W_w, W_b, out);
}